// round 5
// baseline (speedup 1.0000x reference)
#include <cuda_runtime.h>
#include <math.h>

#define HW   4096
#define CFULL 256
#define C4    64
#define BATCH 4

// Scratch: projections [p(4)][b(4)][64][4096] and fused attention output [b][128][4096]
__device__ float g_proj[(size_t)16 * C4 * HW];          // 16 MB
__device__ float g_fused[(size_t)BATCH * 128 * HW];     // 8 MB

// ---------------------------------------------------------------------------
// Kernel 1: fused 1x1-conv projections.  y[p,b,o,hw] = sum_c W[o,c]*x[b,c,hw]+bias
// p: 0=q(cur,Wqk) 1=kl(last,Wkl) 2=kf(fut,Wkf) 3=v(cur,Wv)
// Tiles: BM=64 (all o), BN=128 hw, BK=32. 256 threads, 4x8 micro-tile.
// ---------------------------------------------------------------------------
__global__ __launch_bounds__(256) void proj_kernel(
    const float* __restrict__ last, const float* __restrict__ cur, const float* __restrict__ fut,
    const float* __restrict__ Wqk, const float* __restrict__ bqk,
    const float* __restrict__ Wkl, const float* __restrict__ bkl,
    const float* __restrict__ Wkf, const float* __restrict__ bkf,
    const float* __restrict__ Wv,  const float* __restrict__ bv)
{
    __shared__ float Ws[32 * 65];    // [k][o], padded
    __shared__ float Xs[32 * 128];   // [k][hw]

    int p = blockIdx.y, b = blockIdx.z;
    const float* X; const float* W; const float* bias;
    if (p == 0)      { X = cur;  W = Wqk; bias = bqk; }
    else if (p == 1) { X = last; W = Wkl; bias = bkl; }
    else if (p == 2) { X = fut;  W = Wkf; bias = bkf; }
    else             { X = cur;  W = Wv;  bias = bv;  }
    X += (size_t)b * CFULL * HW;

    int hw0 = blockIdx.x * 128;
    int tid = threadIdx.x;
    int tx = tid & 15, ty = tid >> 4;

    float acc[4][8];
#pragma unroll
    for (int i = 0; i < 4; i++)
#pragma unroll
        for (int j = 0; j < 8; j++) acc[i][j] = 0.f;

    for (int c0 = 0; c0 < CFULL; c0 += 32) {
        __syncthreads();
#pragma unroll
        for (int i = 0; i < 8; i++) {           // 64x32 W tile
            int idx = tid + i * 256;
            int k = idx & 31, o = idx >> 5;
            Ws[k * 65 + o] = W[o * CFULL + c0 + k];
        }
#pragma unroll
        for (int i = 0; i < 16; i++) {          // 32x128 X tile
            int idx = tid + i * 256;
            int j = idx & 127, k = idx >> 7;
            Xs[k * 128 + j] = X[(size_t)(c0 + k) * HW + hw0 + j];
        }
        __syncthreads();
#pragma unroll
        for (int k = 0; k < 32; k++) {
            float a_[4];
#pragma unroll
            for (int i = 0; i < 4; i++) a_[i] = Ws[k * 65 + ty * 4 + i];
            float4 b0 = *(const float4*)&Xs[k * 128 + tx * 8];
            float4 b1 = *(const float4*)&Xs[k * 128 + tx * 8 + 4];
            float bb[8] = {b0.x, b0.y, b0.z, b0.w, b1.x, b1.y, b1.z, b1.w};
#pragma unroll
            for (int i = 0; i < 4; i++)
#pragma unroll
                for (int j = 0; j < 8; j++) acc[i][j] = fmaf(a_[i], bb[j], acc[i][j]);
        }
    }

    float* out = g_proj + ((size_t)(p * 4 + b)) * C4 * HW;
#pragma unroll
    for (int i = 0; i < 4; i++) {
        int o = ty * 4 + i;
        float bo = bias[o];
#pragma unroll
        for (int j = 0; j < 8; j++)
            out[(size_t)o * HW + hw0 + tx * 8 + j] = acc[i][j] + bo;
    }
}

// ---------------------------------------------------------------------------
// Kernel 2: flash attention. For (b, a in {last,future}, qtile):
//   O[q,c] = sum_k softmax_k(q·k_a) * v[c,k]
// Bq=Bk=64, 256 threads (16x16), 4x4 micro-tiles, online softmax.
// smem: Qs[d][q], Ks[d][k] (both 64x64), Vt[k][c] (pad 68), Pt[k][q] (pad 65)
// ---------------------------------------------------------------------------
__global__ __launch_bounds__(256) void attn_kernel()
{
    extern __shared__ float sm[];
    float* Qs = sm;                     // 64*64
    float* Ks = sm + 4096;              // 64*64
    float* Vt = sm + 8192;              // 64*68
    float* Pt = sm + 8192 + 64 * 68;    // 64*65

    int tid = threadIdx.x;
    int tx = tid & 15, ty = tid >> 4;
    int b = blockIdx.z, a = blockIdx.y;
    int q0 = blockIdx.x * 64;

    const float* qb = g_proj + ((size_t)(0 * 4 + b)) * C4 * HW;
    const float* kb = g_proj + ((size_t)((1 + a) * 4 + b)) * C4 * HW;
    const float* vb = g_proj + ((size_t)(3 * 4 + b)) * C4 * HW;

    // load Q tile (d-major)
#pragma unroll
    for (int i = 0; i < 16; i++) {
        int idx = tid + i * 256;
        int q = idx & 63, d = idx >> 6;
        Qs[d * 64 + q] = qb[(size_t)d * HW + q0 + q];
    }

    float acc[4][4];
    float m[4], l[4];
#pragma unroll
    for (int i = 0; i < 4; i++) {
        m[i] = -1e30f; l[i] = 0.f;
#pragma unroll
        for (int j = 0; j < 4; j++) acc[i][j] = 0.f;
    }

    for (int kt = 0; kt < 64; kt++) {
        int k0 = kt * 64;
        __syncthreads();   // prev GEMM2 done reading Vt/Pt before overwrite
#pragma unroll
        for (int i = 0; i < 16; i++) {
            int idx = tid + i * 256;
            int k = idx & 63, c = idx >> 6;
            Ks[c * 64 + k] = kb[(size_t)c * HW + k0 + k];   // c==d here
            Vt[k * 68 + c] = vb[(size_t)c * HW + k0 + k];
        }
        __syncthreads();

        // GEMM1: S[q,k] = sum_d Q[d,q]*K[d,k]
        float s[4][4];
#pragma unroll
        for (int i = 0; i < 4; i++)
#pragma unroll
            for (int j = 0; j < 4; j++) s[i][j] = 0.f;
#pragma unroll
        for (int d = 0; d < 64; d++) {
            float4 av = *(const float4*)&Qs[d * 64 + ty * 4];
            float4 bv = *(const float4*)&Ks[d * 64 + tx * 4];
            float aa[4] = {av.x, av.y, av.z, av.w};
            float bb[4] = {bv.x, bv.y, bv.z, bv.w};
#pragma unroll
            for (int i = 0; i < 4; i++)
#pragma unroll
                for (int j = 0; j < 4; j++) s[i][j] = fmaf(aa[i], bb[j], s[i][j]);
        }

        // online softmax over key axis (reduce across tx = 16 lanes of half-warp)
#pragma unroll
        for (int i = 0; i < 4; i++) {
            float rm = fmaxf(fmaxf(s[i][0], s[i][1]), fmaxf(s[i][2], s[i][3]));
            rm = fmaxf(rm, __shfl_xor_sync(0xffffffffu, rm, 1));
            rm = fmaxf(rm, __shfl_xor_sync(0xffffffffu, rm, 2));
            rm = fmaxf(rm, __shfl_xor_sync(0xffffffffu, rm, 4));
            rm = fmaxf(rm, __shfl_xor_sync(0xffffffffu, rm, 8));
            float mn = fmaxf(m[i], rm);
            float sc = __expf(m[i] - mn);
            float ps = 0.f;
#pragma unroll
            for (int j = 0; j < 4; j++) {
                s[i][j] = __expf(s[i][j] - mn);
                ps += s[i][j];
            }
            ps += __shfl_xor_sync(0xffffffffu, ps, 1);
            ps += __shfl_xor_sync(0xffffffffu, ps, 2);
            ps += __shfl_xor_sync(0xffffffffu, ps, 4);
            ps += __shfl_xor_sync(0xffffffffu, ps, 8);
            l[i] = l[i] * sc + ps;
            m[i] = mn;
#pragma unroll
            for (int j = 0; j < 4; j++) acc[i][j] *= sc;
        }

        // write P transposed: Pt[k][q]
#pragma unroll
        for (int i = 0; i < 4; i++)
#pragma unroll
            for (int j = 0; j < 4; j++)
                Pt[(tx * 4 + j) * 65 + ty * 4 + i] = s[i][j];
        __syncthreads();

        // GEMM2: O[q,c] += sum_k Pt[k,q]*Vt[k,c]
#pragma unroll
        for (int kk = 0; kk < 64; kk++) {
            float4 bv = *(const float4*)&Vt[kk * 68 + tx * 4];
            float bb[4] = {bv.x, bv.y, bv.z, bv.w};
            float aa[4];
#pragma unroll
            for (int i = 0; i < 4; i++) aa[i] = Pt[kk * 65 + ty * 4 + i];
#pragma unroll
            for (int i = 0; i < 4; i++)
#pragma unroll
                for (int j = 0; j < 4; j++) acc[i][j] = fmaf(aa[i], bb[j], acc[i][j]);
        }
    }

    // epilogue: normalize and write fused[b, a*64 + c, q]
    float* fo = g_fused + (size_t)b * 128 * HW + (size_t)a * 64 * HW;
#pragma unroll
    for (int i = 0; i < 4; i++) {
        float inv = 1.f / l[i];
        int q = q0 + ty * 4 + i;
#pragma unroll
        for (int j = 0; j < 4; j++) {
            int c = tx * 4 + j;
            fo[(size_t)c * HW + q] = acc[i][j] * inv;
        }
    }
}

// ---------------------------------------------------------------------------
// Kernel 3: fire conv (128->256) + BN(inference) + residual + ReLU
// fired[o,hw] = sum_c Wfire[o,c]*fused[c,hw] + bfire[o]
// out = relu(cur + fired*inv[o] + shift[o])
// ---------------------------------------------------------------------------
__global__ __launch_bounds__(256) void fire_kernel(
    const float* __restrict__ Wfire, const float* __restrict__ bfire,
    const float* __restrict__ gamma, const float* __restrict__ beta,
    const float* __restrict__ mean,  const float* __restrict__ var,
    const float* __restrict__ cur, float* __restrict__ out)
{
    __shared__ float Ws[32 * 65];
    __shared__ float Xs[32 * 128];

    int b = blockIdx.z;
    int o0 = blockIdx.y * 64;
    int hw0 = blockIdx.x * 128;
    const float* X = g_fused + (size_t)b * 128 * HW;
    int tid = threadIdx.x, tx = tid & 15, ty = tid >> 4;

    float acc[4][8];
#pragma unroll
    for (int i = 0; i < 4; i++)
#pragma unroll
        for (int j = 0; j < 8; j++) acc[i][j] = 0.f;

    for (int c0 = 0; c0 < 128; c0 += 32) {
        __syncthreads();
#pragma unroll
        for (int i = 0; i < 8; i++) {
            int idx = tid + i * 256;
            int k = idx & 31, o = idx >> 5;
            Ws[k * 65 + o] = Wfire[(size_t)(o0 + o) * 128 + c0 + k];
        }
#pragma unroll
        for (int i = 0; i < 16; i++) {
            int idx = tid + i * 256;
            int j = idx & 127, k = idx >> 7;
            Xs[k * 128 + j] = X[(size_t)(c0 + k) * HW + hw0 + j];
        }
        __syncthreads();
#pragma unroll
        for (int k = 0; k < 32; k++) {
            float a_[4];
#pragma unroll
            for (int i = 0; i < 4; i++) a_[i] = Ws[k * 65 + ty * 4 + i];
            float4 b0 = *(const float4*)&Xs[k * 128 + tx * 8];
            float4 b1 = *(const float4*)&Xs[k * 128 + tx * 8 + 4];
            float bb[8] = {b0.x, b0.y, b0.z, b0.w, b1.x, b1.y, b1.z, b1.w};
#pragma unroll
            for (int i = 0; i < 4; i++)
#pragma unroll
                for (int j = 0; j < 8; j++) acc[i][j] = fmaf(a_[i], bb[j], acc[i][j]);
        }
    }

#pragma unroll
    for (int i = 0; i < 4; i++) {
        int o = o0 + ty * 4 + i;
        float inv = gamma[o] * rsqrtf(var[o] + 1e-5f);
        float sh  = beta[o] - mean[o] * inv;
        float bo  = bfire[o];
#pragma unroll
        for (int j = 0; j < 8; j++) {
            size_t idx = ((size_t)b * CFULL + o) * HW + hw0 + tx * 8 + j;
            float fired = (acc[i][j] + bo) * inv + sh;
            float r = cur[idx] + fired;
            out[idx] = fmaxf(r, 0.f);
        }
    }
}

// ---------------------------------------------------------------------------
extern "C" void kernel_launch(void* const* d_in, const int* in_sizes, int n_in,
                              void* d_out, int out_size)
{
    const float* last  = (const float*)d_in[0];
    const float* cur   = (const float*)d_in[1];
    const float* fut   = (const float*)d_in[2];
    const float* Wqk   = (const float*)d_in[3];
    const float* bqk   = (const float*)d_in[4];
    const float* Wkl   = (const float*)d_in[5];
    const float* bkl   = (const float*)d_in[6];
    const float* Wkf   = (const float*)d_in[7];
    const float* bkf   = (const float*)d_in[8];
    const float* Wv    = (const float*)d_in[9];
    const float* bv    = (const float*)d_in[10];
    const float* Wfire = (const float*)d_in[11];
    const float* bfire = (const float*)d_in[12];
    const float* gamma = (const float*)d_in[13];
    const float* beta  = (const float*)d_in[14];
    const float* mean  = (const float*)d_in[15];
    const float* var   = (const float*)d_in[16];
    float* out = (float*)d_out;

    dim3 gA(HW / 128, 4, BATCH);
    proj_kernel<<<gA, 256>>>(last, cur, fut, Wqk, bqk, Wkl, bkl, Wkf, bkf, Wv, bv);

    size_t smB = (size_t)(4096 + 4096 + 64 * 68 + 64 * 65) * sizeof(float); // 66816 B
    cudaFuncSetAttribute(attn_kernel, cudaFuncAttributeMaxDynamicSharedMemorySize, (int)smB);
    dim3 gB(HW / 64, 2, BATCH);
    attn_kernel<<<gB, 256, smB>>>();

    dim3 gC(HW / 128, CFULL / 64, BATCH);
    fire_kernel<<<gC, 256>>>(Wfire, bfire, gamma, beta, mean, var, cur, out);
}